// round 15
// baseline (speedup 1.0000x reference)
#include <cuda_runtime.h>
#include <cuda_fp16.h>
#include <cstdint>
#include <cstddef>

// ---------------------------------------------------------------------------
// Problem constants
// ---------------------------------------------------------------------------
#define NTYPES 6
#define HID    256
#define DV     128
#define CCH    64
#define IMH    192
#define IMW    192
#define GARM   24
#define MAXTILES 816

// ---------------------------------------------------------------------------
// Numerics: all GEMM operands single fp16, fp32 accumulate (measured 4.1e-4).
// Fully fused MLP: layer1 (K=128, bias init) -> relu fp16 in smem ->
// layer2 (K=256) -> relu -> layer3 dot + plain store. No h1 in global memory.
//  B chunk image: 256 rows (n) x 64 fp16 (k), SW128 -> 32KB = 2048 uint4
// ---------------------------------------------------------------------------
__device__ float g_garf[GARM * CCH];
__device__ float g_bias[GARM * HID];                   // garf @ W1[128:192] (fp32)
__device__ uint4 g_B1[6 * 2 * 2048];                   // W1[:128] fp16
__device__ uint4 g_B2[6 * 4 * 2048];                   // W2 fp16

struct P {
    const int* idx[NTYPES];
    int M[NTYPES];
    int rowOff[NTYPES + 1];
    int tileOff[NTYPES + 1];   // cumsum of ceil(M/128)
};

// ---------------------------------------------------------------------------
// Helpers (base-arch PTX only: ldmatrix / mma.sync / cp.async — all sm_80+)
// ---------------------------------------------------------------------------
__device__ __forceinline__ uint32_t smem_u32(const void* p) {
    uint32_t a;
    asm("{ .reg .u64 t; cvta.to.shared.u64 t, %1; cvt.u32.u64 %0, t; }" : "=r"(a) : "l"(p));
    return a;
}
#define SW128(x) ((x) ^ (((x) >> 3) & 0x70))

__device__ __forceinline__ void cpa16(uint32_t s, const void* g) {
    asm volatile("cp.async.cg.shared.global [%0], [%1], 16;" :: "r"(s), "l"(g));
}
#define CP_COMMIT() asm volatile("cp.async.commit_group;" ::: "memory")
#define CP_WAIT0()  asm volatile("cp.async.wait_group 0;" ::: "memory")
#define CP_WAIT1()  asm volatile("cp.async.wait_group 1;" ::: "memory")

__device__ __forceinline__ void ldm_x4(uint32_t* r, uint32_t addr) {
    asm volatile("ldmatrix.sync.aligned.m8n8.x4.shared.b16 {%0,%1,%2,%3}, [%4];"
                 : "=r"(r[0]), "=r"(r[1]), "=r"(r[2]), "=r"(r[3]) : "r"(addr));
}
__device__ __forceinline__ void mma16816(float* d, const uint32_t* a, uint32_t b0, uint32_t b1) {
    asm volatile(
        "mma.sync.aligned.m16n8k16.row.col.f32.f16.f16.f32 "
        "{%0,%1,%2,%3},{%4,%5,%6,%7},{%8,%9},{%0,%1,%2,%3};"
        : "+f"(d[0]), "+f"(d[1]), "+f"(d[2]), "+f"(d[3])
        : "r"(a[0]), "r"(a[1]), "r"(a[2]), "r"(a[3]), "r"(b0), "r"(b1));
}
__device__ __forceinline__ void sts32(uint32_t addr, uint32_t v) {
    asm volatile("st.shared.b32 [%0], %1;" :: "r"(addr), "r"(v) : "memory");
}

__device__ __forceinline__ uint16_t f2h(float x) {
    __half hh = __float2half_rn(x);
    return *reinterpret_cast<uint16_t*>(&hh);
}
__device__ __forceinline__ uint32_t pk16(uint16_t a, uint16_t b) {
    return (uint32_t)a | ((uint32_t)b << 16);
}
__device__ __forceinline__ uint4 pack8(const float* v) {
    return make_uint4(pk16(f2h(v[0]), f2h(v[1])), pk16(f2h(v[2]), f2h(v[3])),
                      pk16(f2h(v[4]), f2h(v[5])), pk16(f2h(v[6]), f2h(v[7])));
}

// ---------------------------------------------------------------------------
// Kernel 1: ROI-align + mean pool via separable 33x33 box-sum.
// One WARP per (garment, channel): lane strides the 1089-sample window
// (34 independent coalesced loads per lane -> DRAM latency fully hidden).
// grid (24, 8), 256 threads = 8 channels per block.
// pros in [32,160] => window strictly interior (no clamping).
// ---------------------------------------------------------------------------
__global__ void roi_garf_kernel(const float* __restrict__ imgs,
                                const float* __restrict__ pros,
                                const int* __restrict__ imgbatch) {
    int g = blockIdx.x;
    int ch = blockIdx.y * 8 + (threadIdx.x >> 5);
    int lane = threadIdx.x & 31;
    int b = imgbatch[g];
    float px = pros[2 * g + 0], py = pros[2 * g + 1];
    float x0f = floorf(px - 15.5f), y0f = floorf(py - 15.5f);
    int qx0 = (int)x0f, qy0 = (int)y0f;
    float fx = (px - 15.5f) - x0f, fy = (py - 15.5f) - y0f;
    const float* im = imgs + ((size_t)(b * CCH + ch)) * (IMH * IMW) + qy0 * IMW + qx0;

    float sum = 0.0f;
    #pragma unroll
    for (int s = lane; s < 1089; s += 32) {
        int pr = s / 33, q = s - pr * 33;
        float wy = (pr == 0) ? (1.0f - fy) : ((pr == 32) ? fy : 1.0f);
        float wx = (q == 0) ? (1.0f - fx) : ((q == 32) ? fx : 1.0f);
        sum += wy * wx * __ldg(im + pr * IMW + q);
    }
    #pragma unroll
    for (int off = 16; off > 0; off >>= 1)
        sum += __shfl_xor_sync(0xFFFFFFFFu, sum, off);
    if (lane == 0) g_garf[g * CCH + ch] = sum * (1.0f / 1024.0f);
}

// ---------------------------------------------------------------------------
// Kernel 2 (prep): 60 blocks, 256 threads.
//   [0, 36)   : weight images (fp16)
//   [36, 60)  : per-garment bias (garf @ W1[128:192], fp32)
// ---------------------------------------------------------------------------
__global__ void prep_kernel(const float* __restrict__ W1,
                            const float* __restrict__ W2,
                            const int* __restrict__ gov, P p) {
    int blk = blockIdx.x, tid = threadIdx.x;
    if (blk < 36) {
        int t = blk / 6, cc = blk % 6, n = tid;
        const float* W;
        uint4* d;
        int c;
        if (cc < 2) {
            c = cc;
            W = W1 + (size_t)t * 192 * 256;
            d = g_B1 + (size_t)(t * 2 + c) * 2048;
        } else {
            c = cc - 2;
            W = W2 + (size_t)t * 256 * 256;
            d = g_B2 + (size_t)(t * 4 + c) * 2048;
        }
        #pragma unroll
        for (int g4 = 0; g4 < 8; g4++) {
            float v[8];
            #pragma unroll
            for (int i = 0; i < 8; i++) v[i] = W[(size_t)(c * 64 + g4 * 8 + i) * 256 + n];
            uint32_t sw = SW128((uint32_t)(n * 128 + g4 * 16));
            d[sw >> 4] = pack8(v);
        }
    } else {
        int bb = blk - 36;
        int t = bb >> 2, j = bb & 3;
        int g = gov[p.idx[t][j * (p.M[t] >> 2)]];
        __shared__ float gf[CCH];
        if (tid < CCH) gf[tid] = g_garf[g * CCH + tid];
        __syncthreads();
        const float* w = W1 + ((size_t)t * 192 + DV) * HID + tid;
        float s = 0.0f;
        #pragma unroll 8
        for (int k = 0; k < CCH; k++) s += gf[k] * w[(size_t)k * HID];
        g_bias[g * HID + tid] = s;
    }
}

// ---------------------------------------------------------------------------
// Kernel 3: FUSED MLP. One CTA = 64 rows x full 256-N through all 3 layers.
// 256 threads, 8 warps (2 wm x 4 wn), warp tile 32x64, acc = 64 fp32/thread.
// grid = 2 * tiles.
// smem layout (1024-aligned):
//   [0, 32K)   R0: layer-1 A images (2 x 8KB used) -> then h1 images (4 x 8KB)
//   [32K, 96K) B region: layer1 = B1 (2 x 32KB); layer2 = B2 double-buffer
//              (layer-3: first 3KB reused as cross-warp partial buffer)
//   [96K, 99K) W3 staging (768 floats)
// cp.async groups: G0=B1c0, G1=B1c1, G2..G5 = B2c0..c3.
// Epilogue: smem cross-warp reduce + plain STG (no atomics, no memset).
// ---------------------------------------------------------------------------
#define FUSED_SMEM (32768 + 65536 + 3072 + 1024)

__global__ __launch_bounds__(256, 2)
void fused_mlp_kernel(const float* __restrict__ xv,
                      const float* __restrict__ W3,
                      const int* __restrict__ gov,
                      float* __restrict__ out, P p) {
    extern __shared__ char dsm[];
    int tid = threadIdx.x, lane = tid & 31, wid = tid >> 5;
    int wm = wid >> 2, wn = wid & 3;              // 2x4 warp grid, 32x64 tiles
    int bx = blockIdx.x;
    int mt = bx >> 1, rhalf = bx & 1;
    int t = 0;
    while (t < NTYPES - 1 && mt >= p.tileOff[t + 1]) t++;
    int m0 = (mt - p.tileOff[t]) * 128 + rhalf * 64;
    int Mt = p.M[t];

    uint32_t sbraw = smem_u32(dsm);
    uint32_t s0 = (sbraw + 1023u) & ~1023u;
    char* alp = dsm + (s0 - sbraw);
    uint32_t sBR = s0 + 32768;
    float* w3s = (float*)(alp + 98304);

    // stage W3[t]
    {
        const float* src = W3 + (size_t)t * (HID * 3);
        for (int i = tid; i < HID * 3; i += 256) w3s[i] = src[i];
    }

    // ---- G0/G1: B1 chunks into B region slots ----
    {
        const uint4* B1 = g_B1 + (size_t)(t * 2) * 2048;
        #pragma unroll
        for (int c = 0; c < 2; c++) {
            uint32_t sB = sBR + (uint32_t)(c * 32768);
            const uint4* B = B1 + (size_t)c * 2048;
            #pragma unroll
            for (int i = tid; i < 2048; i += 256)
                cpa16(sB + i * 16, B + i);
            CP_COMMIT();
        }
    }

    // ---- gather A (once per tile): 64 rows x 128 fp32 -> 2 fp16 SW128 images ----
    {
        int r = tid >> 2;        // 0..63
        int seg = tid & 3;       // 32 floats each
        int grow = m0 + r;
        bool valid = grow < Mt;
        int v = valid ? p.idx[t][grow] : 0;
        const float4* src = (const float4*)(xv + (size_t)v * DV + seg * 32);
        char* cbase = alp + (seg >> 1) * 8192;
        uint32_t colb = (uint32_t)((seg & 1) * 64);
        #pragma unroll
        for (int q = 0; q < 4; q++) {
            float v8[8];
            if (valid) {
                float4 f0 = src[q * 2], f1 = src[q * 2 + 1];
                v8[0] = f0.x; v8[1] = f0.y; v8[2] = f0.z; v8[3] = f0.w;
                v8[4] = f1.x; v8[5] = f1.y; v8[6] = f1.z; v8[7] = f1.w;
            } else {
                #pragma unroll
                for (int i = 0; i < 8; i++) v8[i] = 0.0f;
            }
            uint32_t sw = SW128((uint32_t)(r * 128) + colb + (uint32_t)(q * 16));
            *(uint4*)(cbase + sw) = pack8(v8);
        }
    }

    // ---- accumulators: layer-1 init = per-garment bias ----
    float acc[2][8][4];
    #pragma unroll
    for (int mf = 0; mf < 2; mf++) {
        int r0 = m0 + wm * 32 + mf * 16 + (lane >> 2);
        int r1 = r0 + 8;
        int v0 = p.idx[t][min(r0, Mt - 1)];
        int v1 = p.idx[t][min(r1, Mt - 1)];
        int g0 = gov[v0], g1 = gov[v1];
        #pragma unroll
        for (int nf = 0; nf < 8; nf++) {
            int nl = wn * 64 + nf * 8 + 2 * (lane & 3);
            acc[mf][nf][0] = g_bias[g0 * HID + nl];
            acc[mf][nf][1] = g_bias[g0 * HID + nl + 1];
            acc[mf][nf][2] = g_bias[g1 * HID + nl];
            acc[mf][nf][3] = g_bias[g1 * HID + nl + 1];
        }
    }

    // ldmatrix addressing (SW128: xor (row&7)*16)
    int aRow = lane & 15;
    int aKext = (lane >> 4) * 16;
    int bRow = ((lane >> 4) << 3) + (lane & 7);
    int bKext = ((lane >> 3) & 1) * 16;
    uint32_t xr = (uint32_t)((lane & 7) * 16);
    uint32_t aBase[2], bBase[4];
    #pragma unroll
    for (int mf = 0; mf < 2; mf++) aBase[mf] = (uint32_t)((wm * 32 + mf * 16 + aRow) * 128);
    #pragma unroll
    for (int n2 = 0; n2 < 4; n2++) bBase[n2] = (uint32_t)((wn * 64 + n2 * 16 + bRow) * 128);

    auto compute_chunk = [&](uint32_t sA, uint32_t sB) {
        #pragma unroll
        for (int k16 = 0; k16 < 4; k16++) {
            uint32_t kb = (uint32_t)(k16 * 32);
            uint32_t af[2][4], bf[4][4];
            #pragma unroll
            for (int mf = 0; mf < 2; mf++)
                ldm_x4(af[mf], sA + aBase[mf] + ((kb + (uint32_t)aKext) ^ xr));
            #pragma unroll
            for (int n2 = 0; n2 < 4; n2++)
                ldm_x4(bf[n2], sB + bBase[n2] + ((kb + (uint32_t)bKext) ^ xr));
            #pragma unroll
            for (int mf = 0; mf < 2; mf++)
                #pragma unroll
                for (int nf = 0; nf < 8; nf++)
                    mma16816(acc[mf][nf], af[mf], bf[nf >> 1][(nf & 1) * 2], bf[nf >> 1][(nf & 1) * 2 + 1]);
        }
    };

    auto issueB2 = [&](int c, int slot) {
        const uint4* B = g_B2 + (size_t)(t * 4 + c) * 2048;
        uint32_t bb = sBR + (uint32_t)(slot * 32768);
        #pragma unroll
        for (int i = tid; i < 2048; i += 256)
            cpa16(bb + i * 16, B + i);
        CP_COMMIT();
    };

    // ================= LAYER 1 =================
    CP_WAIT1();          // G0 done
    __syncthreads();     // all G0 + A-image STS visible
    compute_chunk(s0 + 0, sBR + 0);
    __syncthreads();     // slot0 free
    issueB2(0, 0);       // G2
    CP_WAIT1();          // G1 done (G2 pending)
    __syncthreads();
    compute_chunk(s0 + 8192, sBR + 32768);
    __syncthreads();     // done with A images + slot1

    // epilogue 1: relu -> fp16 h1 images (4 x 8KB) in R0; reset acc
    issueB2(1, 1);       // G3 (slot1 free now)
    #pragma unroll
    for (int mf = 0; mf < 2; mf++) {
        #pragma unroll
        for (int nf = 0; nf < 8; nf++) {
            int R0 = wm * 32 + mf * 16 + (lane >> 2);
            int ncl = nf * 8 + 2 * (lane & 3);
            float c0 = fmaxf(acc[mf][nf][0], 0.0f);
            float c1 = fmaxf(acc[mf][nf][1], 0.0f);
            float c2 = fmaxf(acc[mf][nf][2], 0.0f);
            float c3 = fmaxf(acc[mf][nf][3], 0.0f);
            uint32_t base = s0 + (uint32_t)(wn * 8192);   // h1 chunk = wn
            uint32_t off0 = SW128((uint32_t)(R0 * 128 + ncl * 2));
            uint32_t off1 = SW128((uint32_t)((R0 + 8) * 128 + ncl * 2));
            sts32(base + off0, pk16(f2h(c0), f2h(c1)));
            sts32(base + off1, pk16(f2h(c2), f2h(c3)));
            acc[mf][nf][0] = 0.0f; acc[mf][nf][1] = 0.0f;
            acc[mf][nf][2] = 0.0f; acc[mf][nf][3] = 0.0f;
        }
    }
    CP_WAIT1();          // G2 done (G3 pending)
    __syncthreads();     // h1 STS + all G2 visible

    // ================= LAYER 2 =================
    compute_chunk(s0 + 0, sBR + 0);           // h1 c0 x B2 c0
    __syncthreads();
    issueB2(2, 0);       // G4
    CP_WAIT1();          // G3 done
    __syncthreads();
    compute_chunk(s0 + 8192, sBR + 32768);    // h1 c1 x B2 c1
    __syncthreads();
    issueB2(3, 1);       // G5
    CP_WAIT1();          // G4 done
    __syncthreads();
    compute_chunk(s0 + 16384, sBR + 0);       // h1 c2 x B2 c2
    __syncthreads();
    CP_WAIT0();          // G5 done
    __syncthreads();
    compute_chunk(s0 + 24576, sBR + 32768);   // h1 c3 x B2 c3
    // B slot0 free after the sync before c3 -> reuse as partial buffer below.

    // ======= LAYER 3: relu + W3 dot, cross-warp smem reduce, plain store =======
    float* part = (float*)(alp + 32768);   // [wn][64 rows][3] = 768 floats
    #pragma unroll
    for (int mf = 0; mf < 2; mf++) {
        float s0v[3] = {0.f, 0.f, 0.f}, s1v[3] = {0.f, 0.f, 0.f};
        #pragma unroll
        for (int nf = 0; nf < 8; nf++) {
            int nl = wn * 64 + nf * 8 + 2 * (lane & 3);
            const float* w0 = w3s + nl * 3;
            float h0 = fmaxf(acc[mf][nf][0], 0.0f);
            float h1 = fmaxf(acc[mf][nf][1], 0.0f);
            float h2 = fmaxf(acc[mf][nf][2], 0.0f);
            float h3 = fmaxf(acc[mf][nf][3], 0.0f);
            #pragma unroll
            for (int j = 0; j < 3; j++) {
                s0v[j] += h0 * w0[j] + h1 * w0[3 + j];
                s1v[j] += h2 * w0[j] + h3 * w0[3 + j];
            }
        }
        #pragma unroll
        for (int j = 0; j < 3; j++) {
            #pragma unroll
            for (int off = 1; off <= 2; off <<= 1) {
                s0v[j] += __shfl_xor_sync(0xFFFFFFFFu, s0v[j], off);
                s1v[j] += __shfl_xor_sync(0xFFFFFFFFu, s1v[j], off);
            }
        }
        if ((lane & 3) == 0) {
            int r0 = wm * 32 + mf * 16 + (lane >> 2);
            int r1 = r0 + 8;
            #pragma unroll
            for (int j = 0; j < 3; j++) {
                part[(wn * 64 + r0) * 3 + j] = s0v[j];
                part[(wn * 64 + r1) * 3 + j] = s1v[j];
            }
        }
    }
    __syncthreads();
    if (tid < 192) {
        int row = tid / 3, j = tid - row * 3;
        float s = part[(0 * 64 + row) * 3 + j] + part[(1 * 64 + row) * 3 + j]
                + part[(2 * 64 + row) * 3 + j] + part[(3 * 64 + row) * 3 + j];
        int grow = m0 + row;
        if (grow < Mt) {
            int v = p.idx[t][grow];
            out[(size_t)v * 3 + j] = s;
        }
    }
}

// ---------------------------------------------------------------------------
// Launch
// ---------------------------------------------------------------------------
extern "C" void kernel_launch(void* const* d_in, const int* in_sizes, int n_in,
                              void* d_out, int out_size) {
    const float* imgs     = (const float*)d_in[0];
    const float* pros     = (const float*)d_in[1];
    const float* x_verts  = (const float*)d_in[2];
    const float* W1       = (const float*)d_in[3];
    const float* W2       = (const float*)d_in[4];
    const float* W3       = (const float*)d_in[5];
    const int*   imgbatch = (const int*)d_in[6];
    const int*   gov      = (const int*)d_in[7];
    float*       out      = (float*)d_out;

    P p;
    p.rowOff[0] = 0;
    p.tileOff[0] = 0;
    for (int t = 0; t < NTYPES; t++) {
        p.idx[t] = (const int*)d_in[8 + t];
        p.M[t] = in_sizes[8 + t];
        p.rowOff[t + 1] = p.rowOff[t] + p.M[t];
        p.tileOff[t + 1] = p.tileOff[t] + (p.M[t] + 127) / 128;
    }
    int tiles = p.tileOff[NTYPES];

    cudaFuncSetAttribute(fused_mlp_kernel, cudaFuncAttributeMaxDynamicSharedMemorySize, FUSED_SMEM);

    dim3 gG(GARM, 8);
    roi_garf_kernel<<<gG, 256>>>(imgs, pros, imgbatch);

    prep_kernel<<<60, 256>>>(W1, W2, gov, p);

    fused_mlp_kernel<<<2 * tiles, 256, FUSED_SMEM>>>(x_verts, W3, gov, out, p);
}